// round 7
// baseline (speedup 1.0000x reference)
#include <cuda_runtime.h>
#include <cuda_bf16.h>
#include <stdint.h>
#include <math.h>

#define B_ 64
#define T_ 512
#define I_ 256
#define H_ 1024
#define G_ 4096
#define O_ 256

// ---------------- device scratch ----------------
__device__ float g_xproj0[(size_t)T_ * B_ * G_];   // [t][b][4H] fp32
__device__ float g_xproj1[(size_t)T_ * B_ * G_];
__device__ __nv_bfloat16 g_xhi[(size_t)B_ * T_ * I_];
__device__ __nv_bfloat16 g_xlo[(size_t)B_ * T_ * I_];
__device__ __nv_bfloat16 g_wih0hi[(size_t)G_ * I_];
__device__ __nv_bfloat16 g_wih0lo[(size_t)G_ * I_];
__device__ __nv_bfloat16 g_wih1hi[(size_t)G_ * H_];
__device__ __nv_bfloat16 g_wih1lo[(size_t)G_ * H_];
__device__ __nv_bfloat16 g_hs0hi[(size_t)T_ * B_ * H_];  // layer-0 outputs hi/lo
__device__ __nv_bfloat16 g_hs0lo[(size_t)T_ * B_ * H_];
__device__ __nv_bfloat16 g_hhi[2][B_ * H_];
__device__ __nv_bfloat16 g_hlo[2][B_ * H_];
__device__ float g_hlast[B_ * H_];                 // fp32 final h for FC
__device__ unsigned int g_flags[128];              // dataflow: h generation per block

// ---------------- helpers ----------------
__device__ __forceinline__ void ldsm4(uint32_t* r, uint32_t addr) {
    asm volatile("ldmatrix.sync.aligned.m8n8.x4.shared.b16 {%0,%1,%2,%3}, [%4];"
        : "=r"(r[0]), "=r"(r[1]), "=r"(r[2]), "=r"(r[3]) : "r"(addr));
}
__device__ __forceinline__ void ldsm2(uint32_t* r, uint32_t addr) {
    asm volatile("ldmatrix.sync.aligned.m8n8.x2.shared.b16 {%0,%1}, [%2];"
        : "=r"(r[0]), "=r"(r[1]) : "r"(addr));
}
__device__ __forceinline__ void mma16816(float* c, const uint32_t* a, const uint32_t* b) {
    asm volatile("mma.sync.aligned.m16n8k16.row.col.f32.bf16.bf16.f32 "
        "{%0,%1,%2,%3}, {%4,%5,%6,%7}, {%8,%9}, {%0,%1,%2,%3};"
        : "+f"(c[0]), "+f"(c[1]), "+f"(c[2]), "+f"(c[3])
        : "r"(a[0]), "r"(a[1]), "r"(a[2]), "r"(a[3]), "r"(b[0]), "r"(b[1]));
}
__device__ __forceinline__ uint32_t cvta_s(const void* p) {
    return (uint32_t)__cvta_generic_to_shared(p);
}
__device__ __forceinline__ unsigned int ld_acq(const unsigned int* p) {
    unsigned int v;
    asm volatile("ld.acquire.gpu.u32 %0, [%1];" : "=r"(v) : "l"(p) : "memory");
    return v;
}
#define CP_ASYNC16(d, s) asm volatile("cp.async.cg.shared.global [%0], [%1], 16;" :: "r"(d), "l"(s))
#define CP_COMMIT()      asm volatile("cp.async.commit_group;" ::: "memory")
#define CP_WAIT1()       asm volatile("cp.async.wait_group 1;" ::: "memory")
#define CP_WAIT0()       asm volatile("cp.async.wait_group 0;" ::: "memory")

// ---------------- init ----------------
__global__ void init_kernel() {
    int idx = blockIdx.x * blockDim.x + threadIdx.x;
    if (idx < 128) g_flags[idx] = 0u;
    __nv_bfloat16 z = __float2bfloat16(0.f);
    int n = 2 * B_ * H_;
    __nv_bfloat16* ph = (__nv_bfloat16*)g_hhi;
    __nv_bfloat16* pl = (__nv_bfloat16*)g_hlo;
    for (int i = idx; i < n; i += gridDim.x * blockDim.x) { ph[i] = z; pl[i] = z; }
}

// ---------------- fp32 -> bf16 hi/lo split ----------------
__global__ void split_kernel(const float* __restrict__ src,
                             __nv_bfloat16* __restrict__ hi,
                             __nv_bfloat16* __restrict__ lo, int n4) {
    int i = blockIdx.x * blockDim.x + threadIdx.x;
    if (i >= n4) return;
    float4 v = ((const float4*)src)[i];
    __nv_bfloat16 h0 = __float2bfloat16(v.x);
    __nv_bfloat16 h1 = __float2bfloat16(v.y);
    __nv_bfloat16 h2 = __float2bfloat16(v.z);
    __nv_bfloat16 h3 = __float2bfloat16(v.w);
    __nv_bfloat162 a, b;
    a.x = h0; a.y = h1; b.x = h2; b.y = h3;
    ((__nv_bfloat162*)hi)[2 * i] = a;
    ((__nv_bfloat162*)hi)[2 * i + 1] = b;
    a.x = __float2bfloat16(v.x - __bfloat162float(h0));
    a.y = __float2bfloat16(v.y - __bfloat162float(h1));
    b.x = __float2bfloat16(v.z - __bfloat162float(h2));
    b.y = __float2bfloat16(v.w - __bfloat162float(h3));
    ((__nv_bfloat162*)lo)[2 * i] = a;
    ((__nv_bfloat162*)lo)[2 * i + 1] = b;
}

// ---------------- split-bf16 MMA projection GEMM ----------------
__global__ __launch_bounds__(256) void mma_xproj(
    const __nv_bfloat16* __restrict__ Ahi, const __nv_bfloat16* __restrict__ Alo,
    const __nv_bfloat16* __restrict__ Whi, const __nv_bfloat16* __restrict__ Wlo,
    const float* __restrict__ b1, const float* __restrict__ b2,
    float* __restrict__ Cout, int K, int mode)
{
    __shared__ __nv_bfloat16 sAhi[128 * 40], sAlo[128 * 40];
    __shared__ __nv_bfloat16 sBhi[64 * 40],  sBlo[64 * 40];
    __shared__ float sBias[64];

    int tid = threadIdx.x;
    int n0 = blockIdx.x * 64;
    int m0 = blockIdx.y * 128;
    int w = tid >> 5, lane = tid & 31;
    int r0 = w * 16;

    if (tid < 64) sBias[tid] = b1[n0 + tid] + b2[n0 + tid];

    float acc[8][4];
#pragma unroll
    for (int i = 0; i < 8; i++)
#pragma unroll
        for (int j = 0; j < 4; j++) acc[i][j] = 0.f;

    size_t arow[2]; int aoff[2];
#pragma unroll
    for (int it = 0; it < 2; it++) {
        int idx = tid + it * 256;
        int r = idx >> 2, seg = idx & 3;
        int m = m0 + r;
        arow[it] = (mode == 0) ? ((size_t)(m & 63) * T_ + (size_t)(m >> 6)) * (size_t)K + (size_t)(seg * 8)
                               : (size_t)m * (size_t)K + (size_t)(seg * 8);
        aoff[it] = r * 40 + seg * 8;
    }
    int br = tid >> 2, bseg = tid & 3;
    size_t brow = (size_t)(n0 + br) * (size_t)K + (size_t)(bseg * 8);
    int boff = br * 40 + bseg * 8;

    int lrA = (lane & 7) + (lane & 8);
    int lcA = (lane & 16) ? 8 : 0;
    uint32_t aHiB = cvta_s(&sAhi[(r0 + lrA) * 40 + lcA]);
    uint32_t aLoB = cvta_s(&sAlo[(r0 + lrA) * 40 + lcA]);
    int lrB = lane & 7;
    int lcB = (lane & 8) ? 8 : 0;
    uint32_t bHiB = cvta_s(&sBhi[lrB * 40 + lcB]);
    uint32_t bLoB = cvta_s(&sBlo[lrB * 40 + lcB]);

    for (int kc = 0; kc < K; kc += 32) {
        __syncthreads();
#pragma unroll
        for (int it = 0; it < 2; it++) {
            *(uint4*)&sAhi[aoff[it]] = *(const uint4*)(Ahi + arow[it] + kc);
            *(uint4*)&sAlo[aoff[it]] = *(const uint4*)(Alo + arow[it] + kc);
        }
        *(uint4*)&sBhi[boff] = *(const uint4*)(Whi + brow + kc);
        *(uint4*)&sBlo[boff] = *(const uint4*)(Wlo + brow + kc);
        __syncthreads();
#pragma unroll
        for (int ks = 0; ks < 2; ks++) {
            int k0 = ks * 16;
            uint32_t ah[4], al[4];
            ldsm4(ah, aHiB + (uint32_t)(k0 * 2));
            ldsm4(al, aLoB + (uint32_t)(k0 * 2));
#pragma unroll
            for (int nt = 0; nt < 8; nt++) {
                uint32_t bh[2], bl[2];
                uint32_t off = (uint32_t)(nt * 8 * 40 + k0) * 2u;
                ldsm2(bh, bHiB + off);
                ldsm2(bl, bLoB + off);
                mma16816(acc[nt], ah, bh);
                mma16816(acc[nt], ah, bl);
                mma16816(acc[nt], al, bh);
            }
        }
    }

    int g = lane >> 2, tq = lane & 3;
#pragma unroll
    for (int nt = 0; nt < 8; nt++) {
        int col = nt * 8 + tq * 2;
        float bb0 = sBias[col], bb1 = sBias[col + 1];
        size_t mA = (size_t)(m0 + r0 + g) * G_ + n0 + col;
        size_t mB = (size_t)(m0 + r0 + g + 8) * G_ + n0 + col;
        float2 v0 = make_float2(acc[nt][0] + bb0, acc[nt][1] + bb1);
        float2 v1 = make_float2(acc[nt][2] + bb0, acc[nt][3] + bb1);
        *(float2*)&Cout[mA] = v0;
        *(float2*)&Cout[mB] = v1;
    }
}

// ---------------- persistent LSTM recurrence: dataflow-flag pipeline ---------
// 128 blocks x 512 threads (16 warps: 4 row-groups x 4 col-groups).
// Block bid owns h-cols [bid*8, bid*8+8) across all 4 gates (32 gate-cols).
// No grid barrier: block posts flag[bid]=t+1 (release) after writing its
// h-slice; consumers acquire-poll producer flags per chunk before cp.async.
extern __shared__ char smem_dyn[];
__global__ __launch_bounds__(512) void lstm_recur_mma(
    const float* __restrict__ xproj,   // [T][B][4H] fp32
    const float* __restrict__ Whh,     // [4H][H] fp32
    __nv_bfloat16* __restrict__ hshi, __nv_bfloat16* __restrict__ hslo,
    int writeSeq, int writeLast)
{
    __nv_bfloat16* sWhi = (__nv_bfloat16*)smem_dyn;        // 32 x 1032
    __nv_bfloat16* sWlo = sWhi + 32 * 1032;
    __nv_bfloat16* sH   = sWlo + 32 * 1032;                // 2 bufs x (hi,lo) x 64x136
    float* sG = (float*)(sH + 2 * 17408);                  // 64 x 32
    float* sC = sG + 64 * 32;                              // 64 x 8

    int tid = threadIdx.x, w = tid >> 5, lane = tid & 31;
    int bid = blockIdx.x;
    int jbase = bid * 8;
    int grp = bid >> 4;                                    // own chunk group 0..7

    // load + split W_hh into SMEM (once)
    for (int i = tid; i < 32 * 1024; i += 512) {
        int n = i >> 10, k = i & 1023;
        float v = Whh[(size_t)((n >> 3) * H_ + jbase + (n & 7)) * H_ + k];
        __nv_bfloat16 hh = __float2bfloat16(v);
        sWhi[n * 1032 + k] = hh;
        sWlo[n * 1032 + k] = __float2bfloat16(v - __bfloat162float(hh));
    }
    if (tid < 512) sC[tid] = 0.f;

    int r0 = (w & 3) * 16;   // batch-row group (16 rows)
    int cg = w >> 2;         // column group (0..3), 8 gate-cols each
    int lrA = (lane & 7) + (lane & 8);
    int lcA = (lane & 16) ? 8 : 0;
    uint32_t aHiB[2], aLoB[2], dstHi[2], dstLo[2];
#pragma unroll
    for (int bf = 0; bf < 2; bf++) {
        aHiB[bf] = cvta_s(&sH[bf * 17408 + (r0 + lrA) * 136 + lcA]);
        aLoB[bf] = cvta_s(&sH[bf * 17408 + 8704 + (r0 + lrA) * 136 + lcA]);
        dstHi[bf] = cvta_s(&sH[bf * 17408]);
        dstLo[bf] = cvta_s(&sH[bf * 17408 + 8704]);
    }
    // B ldsm4 lane mapping: row = gate-col (lane&7), k-block = (lane>>3)&3
    uint32_t bHiB = cvta_s(&sWhi[(lane & 7) * 1032 + ((lane >> 3) & 3) * 8]);
    uint32_t bLoB = cvta_s(&sWlo[(lane & 7) * 1032 + ((lane >> 3) & 3) * 8]);

    // cp.async per-thread mapping: 2 x 16B per array per chunk
    int pr[2], ps[2];
#pragma unroll
    for (int it = 0; it < 2; it++) {
        int idx = tid + it * 512;
        pr[it] = idx >> 4;            // row 0..63
        ps[it] = (idx & 15) * 8;      // col segment (elements); producer = tid&15
    }
    const unsigned int* myflag[8];
#pragma unroll
    for (int c = 0; c < 8; c++) myflag[c] = &g_flags[c * 16 + (tid & 15)];

    int g = lane >> 2, tq = lane & 3;
    int col = cg * 8 + tq * 2;        // gate-col 0..31
    int q = col >> 3, jj = col & 7;
    int bA = r0 + g, bB = bA + 8;

    __syncthreads();

#define PREFETCH_CHUNK(ch, bf, needed) do {                                   \
    while (ld_acq(myflag[(ch)]) < (needed)) __nanosleep(32);                  \
    int kc_ = (ch) * 128;                                                     \
    _Pragma("unroll")                                                         \
    for (int it = 0; it < 2; it++) {                                          \
        uint32_t so = (uint32_t)(pr[it] * 136 + ps[it]) * 2u;                 \
        CP_ASYNC16(dstHi[(bf)] + so, hrH + pr[it] * H_ + kc_ + ps[it]);       \
        CP_ASYNC16(dstLo[(bf)] + so, hrL + pr[it] * H_ + kc_ + ps[it]);       \
    }                                                                         \
    CP_COMMIT();                                                              \
} while (0)

    for (int t = 0; t < T_; t++) {
        const __nv_bfloat16* hrH = g_hhi[t & 1];
        const __nv_bfloat16* hrL = g_hlo[t & 1];
        unsigned int need = (unsigned int)t;

        PREFETCH_CHUNK(grp, 0, need);

        // hoist xproj loads (DRAM latency hidden behind k-loop)
        size_t xb = (size_t)t * B_ * G_ + (size_t)q * H_ + jbase + jj;
        float2 xA = *(const float2*)&xproj[xb + (size_t)bA * G_];
        float2 xB = *(const float2*)&xproj[xb + (size_t)bB * G_];

        float a0[4], a1[4], a2[4];
#pragma unroll
        for (int j = 0; j < 4; j++) { a0[j] = 0.f; a1[j] = 0.f; a2[j] = 0.f; }

        for (int i = 0; i < 8; i++) {
            int cur = i & 1;
            int ch = (grp + i) & 7;
            if (i < 7) {
                int nch = (grp + i + 1) & 7;
                PREFETCH_CHUNK(nch, cur ^ 1, need);
                CP_WAIT1();
            } else {
                CP_WAIT0();
            }
            __syncthreads();

            int kc = ch * 128;
#pragma unroll
            for (int ks2 = 0; ks2 < 4; ks2++) {
                int k0 = ks2 * 32;
                uint32_t ah0[4], al0[4], ah1[4], al1[4], bh[4], bl[4];
                ldsm4(ah0, aHiB[cur] + (uint32_t)(k0 * 2));
                ldsm4(al0, aLoB[cur] + (uint32_t)(k0 * 2));
                ldsm4(ah1, aHiB[cur] + (uint32_t)((k0 + 16) * 2));
                ldsm4(al1, aLoB[cur] + (uint32_t)((k0 + 16) * 2));
                uint32_t boff2 = (uint32_t)(cg * 8 * 1032 + kc + k0) * 2u;
                ldsm4(bh, bHiB + boff2);
                ldsm4(bl, bLoB + boff2);
                mma16816(a0, ah0, bh);
                mma16816(a1, ah0, bl);
                mma16816(a2, al0, bh);
                mma16816(a0, ah1, bh + 2);
                mma16816(a1, ah1, bl + 2);
                mma16816(a2, al1, bh + 2);
            }
            __syncthreads();
        }

        // gates = acc + xproj  -> sG
        sG[bA * 32 + col]     = a0[0] + a1[0] + a2[0] + xA.x;
        sG[bA * 32 + col + 1] = a0[1] + a1[1] + a2[1] + xA.y;
        sG[bB * 32 + col]     = a0[2] + a1[2] + a2[2] + xB.x;
        sG[bB * 32 + col + 1] = a0[3] + a1[3] + a2[3] + xB.y;
        __syncthreads();

        // cell update: 512 cells/block, 1 per thread
        __nv_bfloat16* hwH = g_hhi[(t + 1) & 1];
        __nv_bfloat16* hwL = g_hlo[(t + 1) & 1];
        {
            int b = tid >> 3, j2 = tid & 7;
            float iv = sG[b * 32 + j2];
            float fv = sG[b * 32 + 8 + j2];
            float gv = sG[b * 32 + 16 + j2];
            float ov = sG[b * 32 + 24 + j2];
            float ig = 1.f / (1.f + expf(-iv));
            float fg = 1.f / (1.f + expf(-fv));
            float gg = tanhf(gv);
            float og = 1.f / (1.f + expf(-ov));
            float cc = fg * sC[b * 8 + j2] + ig * gg;
            sC[b * 8 + j2] = cc;
            float hh = og * tanhf(cc);
            __nv_bfloat16 hb = __float2bfloat16(hh);
            __nv_bfloat16 lb = __float2bfloat16(hh - __bfloat162float(hb));
            int hidx = b * H_ + jbase + j2;
            hwH[hidx] = hb; hwL[hidx] = lb;
            if (writeSeq) {
                size_t sidx = ((size_t)t * B_ + b) * H_ + jbase + j2;
                hshi[sidx] = hb; hslo[sidx] = lb;
            }
            if (writeLast && t == T_ - 1) g_hlast[hidx] = hh;
        }
        __syncthreads();
        if (tid == 0) {
            __threadfence();
            asm volatile("st.release.gpu.u32 [%0], %1;"
                :: "l"(&g_flags[bid]), "r"((unsigned int)(t + 1)) : "memory");
        }
    }
#undef PREFETCH_CHUNK
}

// ---------------- FC head ----------------
__global__ __launch_bounds__(256) void fc_kernel(
    const float* __restrict__ fc_w, const float* __restrict__ fc_b,
    float* __restrict__ out)
{
    __shared__ float sh[H_];
    int b = blockIdx.x, tid = threadIdx.x;
    const float* hlast = g_hlast + (size_t)b * H_;
    for (int i = tid; i < H_; i += 256) sh[i] = hlast[i];
    __syncthreads();
    int o = tid;
    const float* wrow = fc_w + (size_t)o * H_;
    float acc = fc_b[o];
#pragma unroll 8
    for (int k = 0; k < H_; k++) acc += sh[k] * wrow[k];
    out[b * O_ + o] = acc;
}

// ---------------- launch ----------------
#define SMEM_REC ((32*1032*2 + 2*17408) * 2 + 64*32*4 + 64*8*4)

extern "C" void kernel_launch(void* const* d_in, const int* in_sizes, int n_in,
                              void* d_out, int out_size) {
    (void)in_sizes; (void)n_in; (void)out_size;
    const float* x     = (const float*)d_in[0];
    const float* W_ih0 = (const float*)d_in[1];
    const float* W_hh0 = (const float*)d_in[2];
    const float* b_ih0 = (const float*)d_in[3];
    const float* b_hh0 = (const float*)d_in[4];
    const float* W_ih1 = (const float*)d_in[5];
    const float* W_hh1 = (const float*)d_in[6];
    const float* b_ih1 = (const float*)d_in[7];
    const float* b_hh1 = (const float*)d_in[8];
    const float* fc_w  = (const float*)d_in[9];
    const float* fc_b  = (const float*)d_in[10];
    float* out = (float*)d_out;

    float *xp0, *xp1;
    __nv_bfloat16 *xhi, *xlo, *w0hi, *w0lo, *w1hi, *w1lo, *hs0hi, *hs0lo;
    cudaGetSymbolAddress((void**)&xp0, g_xproj0);
    cudaGetSymbolAddress((void**)&xp1, g_xproj1);
    cudaGetSymbolAddress((void**)&xhi, g_xhi);
    cudaGetSymbolAddress((void**)&xlo, g_xlo);
    cudaGetSymbolAddress((void**)&w0hi, g_wih0hi);
    cudaGetSymbolAddress((void**)&w0lo, g_wih0lo);
    cudaGetSymbolAddress((void**)&w1hi, g_wih1hi);
    cudaGetSymbolAddress((void**)&w1lo, g_wih1lo);
    cudaGetSymbolAddress((void**)&hs0hi, g_hs0hi);
    cudaGetSymbolAddress((void**)&hs0lo, g_hs0lo);

    cudaFuncSetAttribute(lstm_recur_mma,
        cudaFuncAttributeMaxDynamicSharedMemorySize, SMEM_REC);

    // splits
    int nx4 = B_ * T_ * I_ / 4;
    split_kernel<<<(nx4 + 255) / 256, 256>>>(x, xhi, xlo, nx4);
    int nw04 = G_ * I_ / 4;
    split_kernel<<<(nw04 + 255) / 256, 256>>>(W_ih0, w0hi, w0lo, nw04);
    int nw14 = G_ * H_ / 4;
    split_kernel<<<(nw14 + 255) / 256, 256>>>(W_ih1, w1hi, w1lo, nw14);

    dim3 pgrid(G_ / 64, (B_ * T_) / 128);

    // layer 0
    mma_xproj<<<pgrid, 256>>>(xhi, xlo, w0hi, w0lo, b_ih0, b_hh0, xp0, I_, 0);
    init_kernel<<<64, 256>>>();
    lstm_recur_mma<<<128, 512, SMEM_REC>>>(xp0, W_hh0, hs0hi, hs0lo, 1, 0);

    // layer 1
    mma_xproj<<<pgrid, 256>>>(hs0hi, hs0lo, w1hi, w1lo, b_ih1, b_hh1, xp1, H_, 1);
    init_kernel<<<64, 256>>>();
    lstm_recur_mma<<<128, 512, SMEM_REC>>>(xp1, W_hh1, hs0hi, hs0lo, 0, 1);

    // head
    fc_kernel<<<64, 256>>>(fc_w, fc_b, out);
}

// round 8
// speedup vs baseline: 1.6207x; 1.6207x over previous
#include <cuda_runtime.h>
#include <cuda_bf16.h>
#include <stdint.h>
#include <math.h>

#define B_ 64
#define T_ 512
#define I_ 256
#define H_ 1024
#define G_ 4096
#define O_ 256

// ---------------- device scratch ----------------
__device__ float g_xproj0[(size_t)T_ * B_ * G_];   // [t][b][4H] fp32
__device__ float g_xproj1[(size_t)T_ * B_ * G_];
__device__ __nv_bfloat16 g_xhi[(size_t)B_ * T_ * I_];
__device__ __nv_bfloat16 g_xlo[(size_t)B_ * T_ * I_];
__device__ __nv_bfloat16 g_wih0hi[(size_t)G_ * I_];
__device__ __nv_bfloat16 g_wih0lo[(size_t)G_ * I_];
__device__ __nv_bfloat16 g_wih1hi[(size_t)G_ * H_];
__device__ __nv_bfloat16 g_wih1lo[(size_t)G_ * H_];
__device__ __nv_bfloat16 g_hs0hi[(size_t)T_ * B_ * H_];  // layer-0 outputs hi/lo
__device__ __nv_bfloat16 g_hs0lo[(size_t)T_ * B_ * H_];
__device__ __nv_bfloat16 g_hhi[2][B_ * H_];
__device__ __nv_bfloat16 g_hlo[2][B_ * H_];
__device__ float g_hlast[B_ * H_];                 // fp32 final h for FC
__device__ unsigned int g_cnt[8 * 32];             // 8 group counters, 128B padded
__device__ unsigned int g_super;                   // super counter (8 arrivals/step)

// ---------------- helpers ----------------
__device__ __forceinline__ void ldsm4(uint32_t* r, uint32_t addr) {
    asm volatile("ldmatrix.sync.aligned.m8n8.x4.shared.b16 {%0,%1,%2,%3}, [%4];"
        : "=r"(r[0]), "=r"(r[1]), "=r"(r[2]), "=r"(r[3]) : "r"(addr));
}
__device__ __forceinline__ void ldsm2(uint32_t* r, uint32_t addr) {
    asm volatile("ldmatrix.sync.aligned.m8n8.x2.shared.b16 {%0,%1}, [%2];"
        : "=r"(r[0]), "=r"(r[1]) : "r"(addr));
}
__device__ __forceinline__ void mma16816(float* c, const uint32_t* a, const uint32_t* b) {
    asm volatile("mma.sync.aligned.m16n8k16.row.col.f32.bf16.bf16.f32 "
        "{%0,%1,%2,%3}, {%4,%5,%6,%7}, {%8,%9}, {%0,%1,%2,%3};"
        : "+f"(c[0]), "+f"(c[1]), "+f"(c[2]), "+f"(c[3])
        : "r"(a[0]), "r"(a[1]), "r"(a[2]), "r"(a[3]), "r"(b[0]), "r"(b[1]));
}
__device__ __forceinline__ uint32_t cvta_s(const void* p) {
    return (uint32_t)__cvta_generic_to_shared(p);
}
__device__ __forceinline__ unsigned int ld_acq(const unsigned int* p) {
    unsigned int v;
    asm volatile("ld.acquire.gpu.u32 %0, [%1];" : "=r"(v) : "l"(p) : "memory");
    return v;
}
#define CP_ASYNC16(d, s) asm volatile("cp.async.cg.shared.global [%0], [%1], 16;" :: "r"(d), "l"(s))
#define CP_COMMIT()      asm volatile("cp.async.commit_group;" ::: "memory")
#define CP_WAIT1()       asm volatile("cp.async.wait_group 1;" ::: "memory")
#define CP_WAIT0()       asm volatile("cp.async.wait_group 0;" ::: "memory")

// ---------------- init ----------------
__global__ void init_kernel() {
    int idx = blockIdx.x * blockDim.x + threadIdx.x;
    if (idx < 8 * 32) g_cnt[idx] = 0u;
    if (idx == 0) g_super = 0u;
    __nv_bfloat16 z = __float2bfloat16(0.f);
    int n = 2 * B_ * H_;
    __nv_bfloat16* ph = (__nv_bfloat16*)g_hhi;
    __nv_bfloat16* pl = (__nv_bfloat16*)g_hlo;
    for (int i = idx; i < n; i += gridDim.x * blockDim.x) { ph[i] = z; pl[i] = z; }
}

// ---------------- fp32 -> bf16 hi/lo split ----------------
__global__ void split_kernel(const float* __restrict__ src,
                             __nv_bfloat16* __restrict__ hi,
                             __nv_bfloat16* __restrict__ lo, int n4) {
    int i = blockIdx.x * blockDim.x + threadIdx.x;
    if (i >= n4) return;
    float4 v = ((const float4*)src)[i];
    __nv_bfloat16 h0 = __float2bfloat16(v.x);
    __nv_bfloat16 h1 = __float2bfloat16(v.y);
    __nv_bfloat16 h2 = __float2bfloat16(v.z);
    __nv_bfloat16 h3 = __float2bfloat16(v.w);
    __nv_bfloat162 a, b;
    a.x = h0; a.y = h1; b.x = h2; b.y = h3;
    ((__nv_bfloat162*)hi)[2 * i] = a;
    ((__nv_bfloat162*)hi)[2 * i + 1] = b;
    a.x = __float2bfloat16(v.x - __bfloat162float(h0));
    a.y = __float2bfloat16(v.y - __bfloat162float(h1));
    b.x = __float2bfloat16(v.z - __bfloat162float(h2));
    b.y = __float2bfloat16(v.w - __bfloat162float(h3));
    ((__nv_bfloat162*)lo)[2 * i] = a;
    ((__nv_bfloat162*)lo)[2 * i + 1] = b;
}

// ---------------- hierarchical grid barrier (128 blocks, 8 groups of 16) ----
__device__ __forceinline__ void gridbar2(int t, int bid) {
    __threadfence();
    __syncthreads();
    if (threadIdx.x == 0) {
        unsigned int r = atomicAdd(&g_cnt[(bid >> 4) * 32], 1u);
        if ((r & 15u) == 15u) atomicAdd(&g_super, 1u);
        unsigned int tgt = 8u * (unsigned int)(t + 1);
        while (ld_acq(&g_super) < tgt) __nanosleep(32);
    }
    __syncthreads();
}

// ---------------- split-bf16 MMA projection GEMM ----------------
__global__ __launch_bounds__(256) void mma_xproj(
    const __nv_bfloat16* __restrict__ Ahi, const __nv_bfloat16* __restrict__ Alo,
    const __nv_bfloat16* __restrict__ Whi, const __nv_bfloat16* __restrict__ Wlo,
    const float* __restrict__ b1, const float* __restrict__ b2,
    float* __restrict__ Cout, int K, int mode)
{
    __shared__ __nv_bfloat16 sAhi[128 * 40], sAlo[128 * 40];
    __shared__ __nv_bfloat16 sBhi[64 * 40],  sBlo[64 * 40];
    __shared__ float sBias[64];

    int tid = threadIdx.x;
    int n0 = blockIdx.x * 64;
    int m0 = blockIdx.y * 128;
    int w = tid >> 5, lane = tid & 31;
    int r0 = w * 16;

    if (tid < 64) sBias[tid] = b1[n0 + tid] + b2[n0 + tid];

    float acc[8][4];
#pragma unroll
    for (int i = 0; i < 8; i++)
#pragma unroll
        for (int j = 0; j < 4; j++) acc[i][j] = 0.f;

    size_t arow[2]; int aoff[2];
#pragma unroll
    for (int it = 0; it < 2; it++) {
        int idx = tid + it * 256;
        int r = idx >> 2, seg = idx & 3;
        int m = m0 + r;
        arow[it] = (mode == 0) ? ((size_t)(m & 63) * T_ + (size_t)(m >> 6)) * (size_t)K + (size_t)(seg * 8)
                               : (size_t)m * (size_t)K + (size_t)(seg * 8);
        aoff[it] = r * 40 + seg * 8;
    }
    int br = tid >> 2, bseg = tid & 3;
    size_t brow = (size_t)(n0 + br) * (size_t)K + (size_t)(bseg * 8);
    int boff = br * 40 + bseg * 8;

    int lrA = (lane & 7) + (lane & 8);
    int lcA = (lane & 16) ? 8 : 0;
    uint32_t aHiB = cvta_s(&sAhi[(r0 + lrA) * 40 + lcA]);
    uint32_t aLoB = cvta_s(&sAlo[(r0 + lrA) * 40 + lcA]);
    int lrB = lane & 7;
    int lcB = (lane & 8) ? 8 : 0;
    uint32_t bHiB = cvta_s(&sBhi[lrB * 40 + lcB]);
    uint32_t bLoB = cvta_s(&sBlo[lrB * 40 + lcB]);

    for (int kc = 0; kc < K; kc += 32) {
        __syncthreads();
#pragma unroll
        for (int it = 0; it < 2; it++) {
            *(uint4*)&sAhi[aoff[it]] = *(const uint4*)(Ahi + arow[it] + kc);
            *(uint4*)&sAlo[aoff[it]] = *(const uint4*)(Alo + arow[it] + kc);
        }
        *(uint4*)&sBhi[boff] = *(const uint4*)(Whi + brow + kc);
        *(uint4*)&sBlo[boff] = *(const uint4*)(Wlo + brow + kc);
        __syncthreads();
#pragma unroll
        for (int ks = 0; ks < 2; ks++) {
            int k0 = ks * 16;
            uint32_t ah[4], al[4];
            ldsm4(ah, aHiB + (uint32_t)(k0 * 2));
            ldsm4(al, aLoB + (uint32_t)(k0 * 2));
#pragma unroll
            for (int nt = 0; nt < 8; nt++) {
                uint32_t bh[2], bl[2];
                uint32_t off = (uint32_t)(nt * 8 * 40 + k0) * 2u;
                ldsm2(bh, bHiB + off);
                ldsm2(bl, bLoB + off);
                mma16816(acc[nt], ah, bh);
                mma16816(acc[nt], ah, bl);
                mma16816(acc[nt], al, bh);
            }
        }
    }

    int g = lane >> 2, tq = lane & 3;
#pragma unroll
    for (int nt = 0; nt < 8; nt++) {
        int col = nt * 8 + tq * 2;
        float bb0 = sBias[col], bb1 = sBias[col + 1];
        size_t mA = (size_t)(m0 + r0 + g) * G_ + n0 + col;
        size_t mB = (size_t)(m0 + r0 + g + 8) * G_ + n0 + col;
        float2 v0 = make_float2(acc[nt][0] + bb0, acc[nt][1] + bb1);
        float2 v1 = make_float2(acc[nt][2] + bb0, acc[nt][3] + bb1);
        *(float2*)&Cout[mA] = v0;
        *(float2*)&Cout[mB] = v1;
    }
}

// ---------------- persistent LSTM recurrence (split-bf16 MMA, cp.async) ------
// 128 blocks x 512 threads (16 warps: 4 row-groups x 4 col-groups).
// Block owns 8 h-columns across all 4 gates (32 gate-cols).
// W_hh hi/lo resident in SMEM; h chunks double-buffered via cp.async.
extern __shared__ char smem_dyn[];
__global__ __launch_bounds__(512) void lstm_recur_mma(
    const float* __restrict__ xproj,   // [T][B][4H] fp32
    const float* __restrict__ Whh,     // [4H][H] fp32
    __nv_bfloat16* __restrict__ hshi, __nv_bfloat16* __restrict__ hslo,
    int writeSeq, int writeLast)
{
    __nv_bfloat16* sWhi = (__nv_bfloat16*)smem_dyn;        // 32 x 1032
    __nv_bfloat16* sWlo = sWhi + 32 * 1032;
    __nv_bfloat16* sH   = sWlo + 32 * 1032;                // 2 bufs x (hi,lo) x 64x136
    float* sG = (float*)(sH + 2 * 17408);                  // 64 x 32
    float* sC = sG + 64 * 32;                              // 64 x 8

    int tid = threadIdx.x, w = tid >> 5, lane = tid & 31;
    int bid = blockIdx.x;
    int jbase = bid * 8;

    // load + split W_hh into SMEM (once)
    for (int i = tid; i < 32 * 1024; i += 512) {
        int n = i >> 10, k = i & 1023;
        float v = Whh[(size_t)((n >> 3) * H_ + jbase + (n & 7)) * H_ + k];
        __nv_bfloat16 hh = __float2bfloat16(v);
        sWhi[n * 1032 + k] = hh;
        sWlo[n * 1032 + k] = __float2bfloat16(v - __bfloat162float(hh));
    }
    if (tid < 512) sC[tid] = 0.f;

    int r0 = (w & 3) * 16;   // batch-row group (16 rows)
    int cg = w >> 2;         // column group (0..3), 8 gate-cols each
    int lrA = (lane & 7) + (lane & 8);
    int lcA = (lane & 16) ? 8 : 0;
    uint32_t aHiB[2], aLoB[2], dstHi[2], dstLo[2];
#pragma unroll
    for (int bf = 0; bf < 2; bf++) {
        aHiB[bf] = cvta_s(&sH[bf * 17408 + (r0 + lrA) * 136 + lcA]);
        aLoB[bf] = cvta_s(&sH[bf * 17408 + 8704 + (r0 + lrA) * 136 + lcA]);
        dstHi[bf] = cvta_s(&sH[bf * 17408]);
        dstLo[bf] = cvta_s(&sH[bf * 17408 + 8704]);
    }
    // B ldsm4 lane mapping: row = gate-col (lane&7), k-block = (lane>>3)&3
    uint32_t bHiB = cvta_s(&sWhi[(lane & 7) * 1032 + ((lane >> 3) & 3) * 8]);
    uint32_t bLoB = cvta_s(&sWlo[(lane & 7) * 1032 + ((lane >> 3) & 3) * 8]);

    // cp.async per-thread mapping: 2 x 16B per array per chunk
    int pr[2], ps[2];
#pragma unroll
    for (int it = 0; it < 2; it++) {
        int idx = tid + it * 512;
        pr[it] = idx >> 4;            // row 0..63
        ps[it] = (idx & 15) * 8;      // col segment (elements)
    }

    int g = lane >> 2, tq = lane & 3;
    int col = cg * 8 + tq * 2;        // gate-col 0..31
    int q = col >> 3, jj = col & 7;
    int bA = r0 + g, bB = bA + 8;

    __syncthreads();

    for (int t = 0; t < T_; t++) {
        const __nv_bfloat16* hrH = g_hhi[t & 1];
        const __nv_bfloat16* hrL = g_hlo[t & 1];

        // prefetch chunk 0
#pragma unroll
        for (int it = 0; it < 2; it++) {
            uint32_t so = (uint32_t)(pr[it] * 136 + ps[it]) * 2u;
            CP_ASYNC16(dstHi[0] + so, hrH + pr[it] * H_ + ps[it]);
            CP_ASYNC16(dstLo[0] + so, hrL + pr[it] * H_ + ps[it]);
        }
        CP_COMMIT();

        // hoist xproj loads (DRAM latency hidden behind k-loop)
        size_t xb = (size_t)t * B_ * G_ + (size_t)q * H_ + jbase + jj;
        float2 xA = *(const float2*)&xproj[xb + (size_t)bA * G_];
        float2 xB = *(const float2*)&xproj[xb + (size_t)bB * G_];

        float a0[4], a1[4], a2[4];
#pragma unroll
        for (int j = 0; j < 4; j++) { a0[j] = 0.f; a1[j] = 0.f; a2[j] = 0.f; }

        for (int ch = 0; ch < 8; ch++) {
            int cur = ch & 1;
            if (ch < 7) {
                int kc2 = (ch + 1) * 128;
#pragma unroll
                for (int it = 0; it < 2; it++) {
                    uint32_t so = (uint32_t)(pr[it] * 136 + ps[it]) * 2u;
                    CP_ASYNC16(dstHi[cur ^ 1] + so, hrH + pr[it] * H_ + kc2 + ps[it]);
                    CP_ASYNC16(dstLo[cur ^ 1] + so, hrL + pr[it] * H_ + kc2 + ps[it]);
                }
                CP_COMMIT();
                CP_WAIT1();
            } else {
                CP_WAIT0();
            }
            __syncthreads();

            int kc = ch * 128;
#pragma unroll
            for (int ks2 = 0; ks2 < 4; ks2++) {
                int k0 = ks2 * 32;
                uint32_t ah0[4], al0[4], ah1[4], al1[4], bh[4], bl[4];
                ldsm4(ah0, aHiB[cur] + (uint32_t)(k0 * 2));
                ldsm4(al0, aLoB[cur] + (uint32_t)(k0 * 2));
                ldsm4(ah1, aHiB[cur] + (uint32_t)((k0 + 16) * 2));
                ldsm4(al1, aLoB[cur] + (uint32_t)((k0 + 16) * 2));
                uint32_t boff2 = (uint32_t)(cg * 8 * 1032 + kc + k0) * 2u;
                ldsm4(bh, bHiB + boff2);
                ldsm4(bl, bLoB + boff2);
                mma16816(a0, ah0, bh);
                mma16816(a1, ah0, bl);
                mma16816(a2, al0, bh);
                mma16816(a0, ah1, bh + 2);
                mma16816(a1, ah1, bl + 2);
                mma16816(a2, al1, bh + 2);
            }
            __syncthreads();
        }

        // gates = acc + xproj  -> sG
        sG[bA * 32 + col]     = a0[0] + a1[0] + a2[0] + xA.x;
        sG[bA * 32 + col + 1] = a0[1] + a1[1] + a2[1] + xA.y;
        sG[bB * 32 + col]     = a0[2] + a1[2] + a2[2] + xB.x;
        sG[bB * 32 + col + 1] = a0[3] + a1[3] + a2[3] + xB.y;
        __syncthreads();

        // cell update: 512 cells/block, 1 per thread
        __nv_bfloat16* hwH = g_hhi[(t + 1) & 1];
        __nv_bfloat16* hwL = g_hlo[(t + 1) & 1];
        {
            int b = tid >> 3, j2 = tid & 7;
            float iv = sG[b * 32 + j2];
            float fv = sG[b * 32 + 8 + j2];
            float gv = sG[b * 32 + 16 + j2];
            float ov = sG[b * 32 + 24 + j2];
            float ig = 1.f / (1.f + expf(-iv));
            float fg = 1.f / (1.f + expf(-fv));
            float gg = tanhf(gv);
            float og = 1.f / (1.f + expf(-ov));
            float cc = fg * sC[b * 8 + j2] + ig * gg;
            sC[b * 8 + j2] = cc;
            float hh = og * tanhf(cc);
            __nv_bfloat16 hb = __float2bfloat16(hh);
            __nv_bfloat16 lb = __float2bfloat16(hh - __bfloat162float(hb));
            int hidx = b * H_ + jbase + j2;
            hwH[hidx] = hb; hwL[hidx] = lb;
            if (writeSeq) {
                size_t sidx = ((size_t)t * B_ + b) * H_ + jbase + j2;
                hshi[sidx] = hb; hslo[sidx] = lb;
            }
            if (writeLast && t == T_ - 1) g_hlast[hidx] = hh;
        }
        gridbar2(t, bid);
    }
}

// ---------------- FC head ----------------
__global__ __launch_bounds__(256) void fc_kernel(
    const float* __restrict__ fc_w, const float* __restrict__ fc_b,
    float* __restrict__ out)
{
    __shared__ float sh[H_];
    int b = blockIdx.x, tid = threadIdx.x;
    const float* hlast = g_hlast + (size_t)b * H_;
    for (int i = tid; i < H_; i += 256) sh[i] = hlast[i];
    __syncthreads();
    int o = tid;
    const float* wrow = fc_w + (size_t)o * H_;
    float acc = fc_b[o];
#pragma unroll 8
    for (int k = 0; k < H_; k++) acc += sh[k] * wrow[k];
    out[b * O_ + o] = acc;
}

// ---------------- launch ----------------
#define SMEM_REC ((32*1032*2 + 2*17408) * 2 + 64*32*4 + 64*8*4)

extern "C" void kernel_launch(void* const* d_in, const int* in_sizes, int n_in,
                              void* d_out, int out_size) {
    (void)in_sizes; (void)n_in; (void)out_size;
    const float* x     = (const float*)d_in[0];
    const float* W_ih0 = (const float*)d_in[1];
    const float* W_hh0 = (const float*)d_in[2];
    const float* b_ih0 = (const float*)d_in[3];
    const float* b_hh0 = (const float*)d_in[4];
    const float* W_ih1 = (const float*)d_in[5];
    const float* W_hh1 = (const float*)d_in[6];
    const float* b_ih1 = (const float*)d_in[7];
    const float* b_hh1 = (const float*)d_in[8];
    const float* fc_w  = (const float*)d_in[9];
    const float* fc_b  = (const float*)d_in[10];
    float* out = (float*)d_out;

    float *xp0, *xp1;
    __nv_bfloat16 *xhi, *xlo, *w0hi, *w0lo, *w1hi, *w1lo, *hs0hi, *hs0lo;
    cudaGetSymbolAddress((void**)&xp0, g_xproj0);
    cudaGetSymbolAddress((void**)&xp1, g_xproj1);
    cudaGetSymbolAddress((void**)&xhi, g_xhi);
    cudaGetSymbolAddress((void**)&xlo, g_xlo);
    cudaGetSymbolAddress((void**)&w0hi, g_wih0hi);
    cudaGetSymbolAddress((void**)&w0lo, g_wih0lo);
    cudaGetSymbolAddress((void**)&w1hi, g_wih1hi);
    cudaGetSymbolAddress((void**)&w1lo, g_wih1lo);
    cudaGetSymbolAddress((void**)&hs0hi, g_hs0hi);
    cudaGetSymbolAddress((void**)&hs0lo, g_hs0lo);

    cudaFuncSetAttribute(lstm_recur_mma,
        cudaFuncAttributeMaxDynamicSharedMemorySize, SMEM_REC);

    // splits
    int nx4 = B_ * T_ * I_ / 4;
    split_kernel<<<(nx4 + 255) / 256, 256>>>(x, xhi, xlo, nx4);
    int nw04 = G_ * I_ / 4;
    split_kernel<<<(nw04 + 255) / 256, 256>>>(W_ih0, w0hi, w0lo, nw04);
    int nw14 = G_ * H_ / 4;
    split_kernel<<<(nw14 + 255) / 256, 256>>>(W_ih1, w1hi, w1lo, nw14);

    dim3 pgrid(G_ / 64, (B_ * T_) / 128);

    // layer 0
    mma_xproj<<<pgrid, 256>>>(xhi, xlo, w0hi, w0lo, b_ih0, b_hh0, xp0, I_, 0);
    init_kernel<<<64, 256>>>();
    lstm_recur_mma<<<128, 512, SMEM_REC>>>(xp0, W_hh0, hs0hi, hs0lo, 1, 0);

    // layer 1
    mma_xproj<<<pgrid, 256>>>(hs0hi, hs0lo, w1hi, w1lo, b_ih1, b_hh1, xp1, H_, 1);
    init_kernel<<<64, 256>>>();
    lstm_recur_mma<<<128, 512, SMEM_REC>>>(xp1, W_hh1, hs0hi, hs0lo, 0, 1);

    // head
    fc_kernel<<<64, 256>>>(fc_w, fc_b, out);
}

// round 9
// speedup vs baseline: 2.3021x; 1.4204x over previous
#include <cuda_runtime.h>
#include <cuda_bf16.h>
#include <cuda_fp16.h>
#include <stdint.h>
#include <math.h>

#define B_ 64
#define T_ 512
#define I_ 256
#define H_ 1024
#define G_ 4096
#define O_ 256

// ---------------- device scratch ----------------
__device__ float g_xproj0[(size_t)T_ * B_ * G_];   // [t][b][4H] fp32
__device__ float g_xproj1[(size_t)T_ * B_ * G_];
__device__ __nv_bfloat16 g_xhi[(size_t)B_ * T_ * I_];
__device__ __nv_bfloat16 g_xlo[(size_t)B_ * T_ * I_];
__device__ __nv_bfloat16 g_wih0hi[(size_t)G_ * I_];
__device__ __nv_bfloat16 g_wih0lo[(size_t)G_ * I_];
__device__ __nv_bfloat16 g_wih1hi[(size_t)G_ * H_];
__device__ __nv_bfloat16 g_wih1lo[(size_t)G_ * H_];
__device__ __nv_bfloat16 g_hs0hi[(size_t)T_ * B_ * H_];  // layer-0 outputs hi/lo (for proj)
__device__ __nv_bfloat16 g_hs0lo[(size_t)T_ * B_ * H_];
__device__ __half g_hf[2][B_ * H_];                // recurrent h, single fp16
__device__ float g_hlast[B_ * H_];                 // fp32 final h for FC
__device__ unsigned int g_cnt[8 * 32];             // 8 group counters, 128B padded
__device__ unsigned int g_super;                   // super counter (8 arrivals/step)

// ---------------- helpers ----------------
__device__ __forceinline__ void ldsm4(uint32_t* r, uint32_t addr) {
    asm volatile("ldmatrix.sync.aligned.m8n8.x4.shared.b16 {%0,%1,%2,%3}, [%4];"
        : "=r"(r[0]), "=r"(r[1]), "=r"(r[2]), "=r"(r[3]) : "r"(addr));
}
__device__ __forceinline__ void ldsm2(uint32_t* r, uint32_t addr) {
    asm volatile("ldmatrix.sync.aligned.m8n8.x2.shared.b16 {%0,%1}, [%2];"
        : "=r"(r[0]), "=r"(r[1]) : "r"(addr));
}
// bf16 mma (projections)
__device__ __forceinline__ void mma16816(float* c, const uint32_t* a, const uint32_t* b) {
    asm volatile("mma.sync.aligned.m16n8k16.row.col.f32.bf16.bf16.f32 "
        "{%0,%1,%2,%3}, {%4,%5,%6,%7}, {%8,%9}, {%0,%1,%2,%3};"
        : "+f"(c[0]), "+f"(c[1]), "+f"(c[2]), "+f"(c[3])
        : "r"(a[0]), "r"(a[1]), "r"(a[2]), "r"(a[3]), "r"(b[0]), "r"(b[1]));
}
// fp16 mma (recurrence)
__device__ __forceinline__ void mma16816h(float* c, const uint32_t* a, const uint32_t* b) {
    asm volatile("mma.sync.aligned.m16n8k16.row.col.f32.f16.f16.f32 "
        "{%0,%1,%2,%3}, {%4,%5,%6,%7}, {%8,%9}, {%0,%1,%2,%3};"
        : "+f"(c[0]), "+f"(c[1]), "+f"(c[2]), "+f"(c[3])
        : "r"(a[0]), "r"(a[1]), "r"(a[2]), "r"(a[3]), "r"(b[0]), "r"(b[1]));
}
__device__ __forceinline__ uint32_t cvta_s(const void* p) {
    return (uint32_t)__cvta_generic_to_shared(p);
}
__device__ __forceinline__ unsigned int ld_acq(const unsigned int* p) {
    unsigned int v;
    asm volatile("ld.acquire.gpu.u32 %0, [%1];" : "=r"(v) : "l"(p) : "memory");
    return v;
}
#define CP_ASYNC16(d, s) asm volatile("cp.async.cg.shared.global [%0], [%1], 16;" :: "r"(d), "l"(s))
#define CP_COMMIT()      asm volatile("cp.async.commit_group;" ::: "memory")
#define CP_WAIT2()       asm volatile("cp.async.wait_group 2;" ::: "memory")
#define CP_WAIT1()       asm volatile("cp.async.wait_group 1;" ::: "memory")
#define CP_WAIT0()       asm volatile("cp.async.wait_group 0;" ::: "memory")

// ---------------- init ----------------
__global__ void init_kernel() {
    int idx = blockIdx.x * blockDim.x + threadIdx.x;
    if (idx < 8 * 32) g_cnt[idx] = 0u;
    if (idx == 0) g_super = 0u;
    __half z = __float2half(0.f);
    int n = 2 * B_ * H_;
    __half* ph = (__half*)g_hf;
    for (int i = idx; i < n; i += gridDim.x * blockDim.x) ph[i] = z;
}

// ---------------- fp32 -> bf16 hi/lo split (projection operands) ------------
__global__ void split_kernel(const float* __restrict__ src,
                             __nv_bfloat16* __restrict__ hi,
                             __nv_bfloat16* __restrict__ lo, int n4) {
    int i = blockIdx.x * blockDim.x + threadIdx.x;
    if (i >= n4) return;
    float4 v = ((const float4*)src)[i];
    __nv_bfloat16 h0 = __float2bfloat16(v.x);
    __nv_bfloat16 h1 = __float2bfloat16(v.y);
    __nv_bfloat16 h2 = __float2bfloat16(v.z);
    __nv_bfloat16 h3 = __float2bfloat16(v.w);
    __nv_bfloat162 a, b;
    a.x = h0; a.y = h1; b.x = h2; b.y = h3;
    ((__nv_bfloat162*)hi)[2 * i] = a;
    ((__nv_bfloat162*)hi)[2 * i + 1] = b;
    a.x = __float2bfloat16(v.x - __bfloat162float(h0));
    a.y = __float2bfloat16(v.y - __bfloat162float(h1));
    b.x = __float2bfloat16(v.z - __bfloat162float(h2));
    b.y = __float2bfloat16(v.w - __bfloat162float(h3));
    ((__nv_bfloat162*)lo)[2 * i] = a;
    ((__nv_bfloat162*)lo)[2 * i + 1] = b;
}

// ---------------- hierarchical grid barrier (128 blocks, 8 groups of 16) ----
__device__ __forceinline__ void gridbar2(int t, int bid) {
    __threadfence();
    __syncthreads();
    if (threadIdx.x == 0) {
        unsigned int r = atomicAdd(&g_cnt[(bid >> 4) * 32], 1u);
        if ((r & 15u) == 15u) atomicAdd(&g_super, 1u);
        unsigned int tgt = 8u * (unsigned int)(t + 1);
        while (ld_acq(&g_super) < tgt) __nanosleep(32);
    }
    __syncthreads();
}

// ---------------- split-bf16 MMA projection GEMM (unchanged) ----------------
__global__ __launch_bounds__(256) void mma_xproj(
    const __nv_bfloat16* __restrict__ Ahi, const __nv_bfloat16* __restrict__ Alo,
    const __nv_bfloat16* __restrict__ Whi, const __nv_bfloat16* __restrict__ Wlo,
    const float* __restrict__ b1, const float* __restrict__ b2,
    float* __restrict__ Cout, int K, int mode)
{
    __shared__ __nv_bfloat16 sAhi[128 * 40], sAlo[128 * 40];
    __shared__ __nv_bfloat16 sBhi[64 * 40],  sBlo[64 * 40];
    __shared__ float sBias[64];

    int tid = threadIdx.x;
    int n0 = blockIdx.x * 64;
    int m0 = blockIdx.y * 128;
    int w = tid >> 5, lane = tid & 31;
    int r0 = w * 16;

    if (tid < 64) sBias[tid] = b1[n0 + tid] + b2[n0 + tid];

    float acc[8][4];
#pragma unroll
    for (int i = 0; i < 8; i++)
#pragma unroll
        for (int j = 0; j < 4; j++) acc[i][j] = 0.f;

    size_t arow[2]; int aoff[2];
#pragma unroll
    for (int it = 0; it < 2; it++) {
        int idx = tid + it * 256;
        int r = idx >> 2, seg = idx & 3;
        int m = m0 + r;
        arow[it] = (mode == 0) ? ((size_t)(m & 63) * T_ + (size_t)(m >> 6)) * (size_t)K + (size_t)(seg * 8)
                               : (size_t)m * (size_t)K + (size_t)(seg * 8);
        aoff[it] = r * 40 + seg * 8;
    }
    int br = tid >> 2, bseg = tid & 3;
    size_t brow = (size_t)(n0 + br) * (size_t)K + (size_t)(bseg * 8);
    int boff = br * 40 + bseg * 8;

    int lrA = (lane & 7) + (lane & 8);
    int lcA = (lane & 16) ? 8 : 0;
    uint32_t aHiB = cvta_s(&sAhi[(r0 + lrA) * 40 + lcA]);
    uint32_t aLoB = cvta_s(&sAlo[(r0 + lrA) * 40 + lcA]);
    int lrB = lane & 7;
    int lcB = (lane & 8) ? 8 : 0;
    uint32_t bHiB = cvta_s(&sBhi[lrB * 40 + lcB]);
    uint32_t bLoB = cvta_s(&sBlo[lrB * 40 + lcB]);

    for (int kc = 0; kc < K; kc += 32) {
        __syncthreads();
#pragma unroll
        for (int it = 0; it < 2; it++) {
            *(uint4*)&sAhi[aoff[it]] = *(const uint4*)(Ahi + arow[it] + kc);
            *(uint4*)&sAlo[aoff[it]] = *(const uint4*)(Alo + arow[it] + kc);
        }
        *(uint4*)&sBhi[boff] = *(const uint4*)(Whi + brow + kc);
        *(uint4*)&sBlo[boff] = *(const uint4*)(Wlo + brow + kc);
        __syncthreads();
#pragma unroll
        for (int ks = 0; ks < 2; ks++) {
            int k0 = ks * 16;
            uint32_t ah[4], al[4];
            ldsm4(ah, aHiB + (uint32_t)(k0 * 2));
            ldsm4(al, aLoB + (uint32_t)(k0 * 2));
#pragma unroll
            for (int nt = 0; nt < 8; nt++) {
                uint32_t bh[2], bl[2];
                uint32_t off = (uint32_t)(nt * 8 * 40 + k0) * 2u;
                ldsm2(bh, bHiB + off);
                ldsm2(bl, bLoB + off);
                mma16816(acc[nt], ah, bh);
                mma16816(acc[nt], ah, bl);
                mma16816(acc[nt], al, bh);
            }
        }
    }

    int g = lane >> 2, tq = lane & 3;
#pragma unroll
    for (int nt = 0; nt < 8; nt++) {
        int col = nt * 8 + tq * 2;
        float bb0 = sBias[col], bb1 = sBias[col + 1];
        size_t mA = (size_t)(m0 + r0 + g) * G_ + n0 + col;
        size_t mB = (size_t)(m0 + r0 + g + 8) * G_ + n0 + col;
        float2 v0 = make_float2(acc[nt][0] + bb0, acc[nt][1] + bb1);
        float2 v1 = make_float2(acc[nt][2] + bb0, acc[nt][3] + bb1);
        *(float2*)&Cout[mA] = v0;
        *(float2*)&Cout[mB] = v1;
    }
}

// ---------------- persistent LSTM recurrence: fp16 2-term, k-split ----------
// 128 blocks x 512 threads. Warp w: rowg=w&3 (16 rows), colg=(w>>2)&1 (16 cols),
// ks=w>>3 (k-half of each 128-col chunk). Block owns 8 h-cols (32 gate-cols).
// W_hh fp16 hi/lo resident in SMEM; h (single fp16) 4-buffer cp.async pipeline.
extern __shared__ char smem_dyn[];
__global__ __launch_bounds__(512) void lstm_recur_mma(
    const float* __restrict__ xproj,   // [T][B][4H] fp32
    const float* __restrict__ Whh,     // [4H][H] fp32
    __nv_bfloat16* __restrict__ hshi, __nv_bfloat16* __restrict__ hslo,
    int writeSeq, int writeLast)
{
    __half* sWhi = (__half*)smem_dyn;                      // 32 x 1032
    __half* sWlo = sWhi + 32 * 1032;
    __half* sH   = sWlo + 32 * 1032;                       // 4 bufs x 64x136
    float* sG  = (float*)(sH + 4 * 64 * 136);              // ks=0 partials, 64x32
    float* sG2 = sG + 64 * 32;                             // ks=1 partials
    float* sC  = sG2 + 64 * 32;                            // 64 x 8 cell state

    int tid = threadIdx.x, w = tid >> 5, lane = tid & 31;
    int bid = blockIdx.x;
    int jbase = bid * 8;

    // load + split W_hh into SMEM fp16 hi/lo (once)
    for (int i = tid; i < 32 * 1024; i += 512) {
        int n = i >> 10, k = i & 1023;
        float v = Whh[(size_t)((n >> 3) * H_ + jbase + (n & 7)) * H_ + k];
        __half hh = __float2half(v);
        sWhi[n * 1032 + k] = hh;
        sWlo[n * 1032 + k] = __float2half(v - __half2float(hh));
    }
    if (tid < 512) sC[tid] = 0.f;

    int rowg = w & 3, colg = (w >> 2) & 1, ks = w >> 3;
    int r0 = rowg * 16;
    int lrA = (lane & 7) + (lane & 8);
    int lcA = (lane & 16) ? 8 : 0;
    uint32_t aB[4], dstB[4];
#pragma unroll
    for (int bf = 0; bf < 4; bf++) {
        aB[bf]  = cvta_s(&sH[bf * 8704 + (r0 + lrA) * 136 + ks * 64 + lcA]);
        dstB[bf] = cvta_s(&sH[bf * 8704]);
    }
    // B bases: two col-tiles (8 gate-cols each) at colg*16 and colg*16+8
    int bRow = (lane & 7);
    int bK   = ((lane >> 3) & 3) * 8;
    uint32_t bHi0 = cvta_s(&sWhi[(colg * 16 + bRow) * 1032 + ks * 64 + bK]);
    uint32_t bLo0 = cvta_s(&sWlo[(colg * 16 + bRow) * 1032 + ks * 64 + bK]);
    uint32_t bHi1 = bHi0 + (uint32_t)(8 * 1032 * 2);
    uint32_t bLo1 = bLo0 + (uint32_t)(8 * 1032 * 2);

    // cp.async mapping: 16KB/chunk = 1024 x 16B; 2 per thread
    int pr[2], ps[2];
#pragma unroll
    for (int it = 0; it < 2; it++) {
        int idx = tid + it * 512;
        pr[it] = idx >> 4;            // row 0..63
        ps[it] = (idx & 15) * 8;      // col segment (8 fp16 = 16B)
    }

    int g = lane >> 2, tq = lane & 3;
    int colA = colg * 16 + tq * 2;    // col-tile 0 cols
    int colB = colA + 8;              // col-tile 1 cols
    int bA = r0 + g, bB = bA + 8;
    float* sGx = ks ? sG2 : sG;

    // cell-update thread mapping + xproj addresses
    int cb = tid >> 3, cj = tid & 7;
    const float* xpb = xproj + (size_t)cb * G_ + jbase + cj;

    __syncthreads();

#define PREF(ch, bf) do {                                                     \
    int kc_ = (ch) * 128;                                                     \
    _Pragma("unroll")                                                         \
    for (int it = 0; it < 2; it++) {                                          \
        uint32_t so = (uint32_t)(pr[it] * 136 + ps[it]) * 2u;                 \
        CP_ASYNC16(dstB[(bf)] + so, hr + pr[it] * H_ + kc_ + ps[it]);         \
    }                                                                         \
    CP_COMMIT();                                                              \
} while (0)

    for (int t = 0; t < T_; t++) {
        const __half* hr = g_hf[t & 1];

        PREF(0, 0);
        PREF(1, 1);

        // prefetch this step's xproj gate values (cell-update layout)
        size_t xt = (size_t)t * B_ * G_;
        float xg0 = xpb[xt];
        float xg1 = xpb[xt + 1 * H_];
        float xg2 = xpb[xt + 2 * H_];
        float xg3 = xpb[xt + 3 * H_];

        float acc[2][2][4];
#pragma unroll
        for (int ct = 0; ct < 2; ct++)
#pragma unroll
            for (int tm = 0; tm < 2; tm++)
#pragma unroll
                for (int j = 0; j < 4; j++) acc[ct][tm][j] = 0.f;

        for (int ch = 0; ch < 8; ch++) {
            int cur = ch & 3;
            if (ch < 6) { PREF(ch + 2, (ch + 2) & 3); CP_WAIT2(); }
            else if (ch == 6) { CP_WAIT1(); }
            else { CP_WAIT0(); }
            __syncthreads();

            int kc = ch * 128;
#pragma unroll
            for (int kg = 0; kg < 2; kg++) {
                uint32_t koff = (uint32_t)(kg * 32) * 2u;
                uint32_t a0[4], a1[4];
                ldsm4(a0, aB[cur] + koff);
                ldsm4(a1, aB[cur] + koff + 32);
                uint32_t bo = (uint32_t)(kc + kg * 32) * 2u;
                uint32_t bh[4], bl[4];
                ldsm4(bh, bHi0 + bo);
                ldsm4(bl, bLo0 + bo);
                mma16816h(acc[0][0], a0, bh);
                mma16816h(acc[0][0], a1, bh + 2);
                mma16816h(acc[0][1], a0, bl);
                mma16816h(acc[0][1], a1, bl + 2);
                uint32_t bh1[4], bl1[4];
                ldsm4(bh1, bHi1 + bo);
                ldsm4(bl1, bLo1 + bo);
                mma16816h(acc[1][0], a0, bh1);
                mma16816h(acc[1][0], a1, bh1 + 2);
                mma16816h(acc[1][1], a0, bl1);
                mma16816h(acc[1][1], a1, bl1 + 2);
            }
        }

        // partial gate sums -> sG (ks=0) / sG2 (ks=1)
        {
            float2 vA0 = make_float2(acc[0][0][0] + acc[0][1][0], acc[0][0][1] + acc[0][1][1]);
            float2 vB0 = make_float2(acc[0][0][2] + acc[0][1][2], acc[0][0][3] + acc[0][1][3]);
            float2 vA1 = make_float2(acc[1][0][0] + acc[1][1][0], acc[1][0][1] + acc[1][1][1]);
            float2 vB1 = make_float2(acc[1][0][2] + acc[1][1][2], acc[1][0][3] + acc[1][1][3]);
            *(float2*)&sGx[bA * 32 + colA] = vA0;
            *(float2*)&sGx[bB * 32 + colA] = vB0;
            *(float2*)&sGx[bA * 32 + colB] = vA1;
            *(float2*)&sGx[bB * 32 + colB] = vB1;
        }
        __syncthreads();

        // cell update: 512 cells/block, 1 per thread
        __half* hw = g_hf[(t + 1) & 1];
        {
            float iv = sG[cb * 32 + cj]      + sG2[cb * 32 + cj]      + xg0;
            float fv = sG[cb * 32 + 8 + cj]  + sG2[cb * 32 + 8 + cj]  + xg1;
            float gv = sG[cb * 32 + 16 + cj] + sG2[cb * 32 + 16 + cj] + xg2;
            float ov = sG[cb * 32 + 24 + cj] + sG2[cb * 32 + 24 + cj] + xg3;
            float ig = 1.f / (1.f + expf(-iv));
            float fg = 1.f / (1.f + expf(-fv));
            float gg = tanhf(gv);
            float og = 1.f / (1.f + expf(-ov));
            float cc = fg * sC[cb * 8 + cj] + ig * gg;
            sC[cb * 8 + cj] = cc;
            float hh = og * tanhf(cc);
            int hidx = cb * H_ + jbase + cj;
            hw[hidx] = __float2half(hh);
            if (writeSeq) {
                __nv_bfloat16 hb = __float2bfloat16(hh);
                size_t sidx = ((size_t)t * B_ + cb) * H_ + jbase + cj;
                hshi[sidx] = hb;
                hslo[sidx] = __float2bfloat16(hh - __bfloat162float(hb));
            }
            if (writeLast && t == T_ - 1) g_hlast[hidx] = hh;
        }
        gridbar2(t, bid);
    }
#undef PREF
}

// ---------------- FC head ----------------
__global__ __launch_bounds__(256) void fc_kernel(
    const float* __restrict__ fc_w, const float* __restrict__ fc_b,
    float* __restrict__ out)
{
    __shared__ float sh[H_];
    int b = blockIdx.x, tid = threadIdx.x;
    const float* hlast = g_hlast + (size_t)b * H_;
    for (int i = tid; i < H_; i += 256) sh[i] = hlast[i];
    __syncthreads();
    int o = tid;
    const float* wrow = fc_w + (size_t)o * H_;
    float acc = fc_b[o];
#pragma unroll 8
    for (int k = 0; k < H_; k++) acc += sh[k] * wrow[k];
    out[b * O_ + o] = acc;
}

// ---------------- launch ----------------
// W: 2*32*1032 fp16 + h: 4*64*136 fp16 + sG/sG2: 2*2048 f32 + sC: 512 f32
#define SMEM_REC ((2*32*1032 + 4*64*136) * 2 + (2*64*32 + 64*8) * 4)

extern "C" void kernel_launch(void* const* d_in, const int* in_sizes, int n_in,
                              void* d_out, int out_size) {
    (void)in_sizes; (void)n_in; (void)out_size;
    const float* x     = (const float*)d_in[0];
    const float* W_ih0 = (const float*)d_in[1];
    const float* W_hh0 = (const float*)d_in[2];
    const float* b_ih0 = (const float*)d_in[3];
    const float* b_hh0 = (const float*)d_in[4];
    const float* W_ih1 = (const float*)d_in[5];
    const float* W_hh1 = (const float*)d_in[6];
    const float* b_ih1 = (const float*)d_in[7];
    const float* b_hh1 = (const float*)d_in[8];
    const float* fc_w  = (const float*)d_in[9];
    const float* fc_b  = (const float*)d_in[10];
    float* out = (float*)d_out;

    float *xp0, *xp1;
    __nv_bfloat16 *xhi, *xlo, *w0hi, *w0lo, *w1hi, *w1lo, *hs0hi, *hs0lo;
    cudaGetSymbolAddress((void**)&xp0, g_xproj0);
    cudaGetSymbolAddress((void**)&xp1, g_xproj1);
    cudaGetSymbolAddress((void**)&xhi, g_xhi);
    cudaGetSymbolAddress((void**)&xlo, g_xlo);
    cudaGetSymbolAddress((void**)&w0hi, g_wih0hi);
    cudaGetSymbolAddress((void**)&w0lo, g_wih0lo);
    cudaGetSymbolAddress((void**)&w1hi, g_wih1hi);
    cudaGetSymbolAddress((void**)&w1lo, g_wih1lo);
    cudaGetSymbolAddress((void**)&hs0hi, g_hs0hi);
    cudaGetSymbolAddress((void**)&hs0lo, g_hs0lo);

    cudaFuncSetAttribute(lstm_recur_mma,
        cudaFuncAttributeMaxDynamicSharedMemorySize, SMEM_REC);

    // splits (projection operands, bf16 3-term)
    int nx4 = B_ * T_ * I_ / 4;
    split_kernel<<<(nx4 + 255) / 256, 256>>>(x, xhi, xlo, nx4);
    int nw04 = G_ * I_ / 4;
    split_kernel<<<(nw04 + 255) / 256, 256>>>(W_ih0, w0hi, w0lo, nw04);
    int nw14 = G_ * H_ / 4;
    split_kernel<<<(nw14 + 255) / 256, 256>>>(W_ih1, w1hi, w1lo, nw14);

    dim3 pgrid(G_ / 64, (B_ * T_) / 128);

    // layer 0
    mma_xproj<<<pgrid, 256>>>(xhi, xlo, w0hi, w0lo, b_ih0, b_hh0, xp0, I_, 0);
    init_kernel<<<64, 256>>>();
    lstm_recur_mma<<<128, 512, SMEM_REC>>>(xp0, W_hh0, hs0hi, hs0lo, 1, 0);

    // layer 1
    mma_xproj<<<pgrid, 256>>>(hs0hi, hs0lo, w1hi, w1lo, b_ih1, b_hh1, xp1, H_, 1);
    init_kernel<<<64, 256>>>();
    lstm_recur_mma<<<128, 512, SMEM_REC>>>(xp1, W_hh1, hs0hi, hs0lo, 0, 1);

    // head
    fc_kernel<<<64, 256>>>(fc_w, fc_b, out);
}

// round 10
// speedup vs baseline: 2.5348x; 1.1011x over previous
#include <cuda_runtime.h>
#include <cuda_bf16.h>
#include <cuda_fp16.h>
#include <stdint.h>
#include <math.h>

#define B_ 64
#define T_ 512
#define I_ 256
#define H_ 1024
#define G_ 4096
#define O_ 256

// ---------------- device scratch ----------------
__device__ float g_xproj0[(size_t)T_ * B_ * G_];   // [t][b][4H] fp32
__device__ float g_xproj1[(size_t)T_ * B_ * G_];
__device__ __nv_bfloat16 g_xhi[(size_t)B_ * T_ * I_];
__device__ __nv_bfloat16 g_xlo[(size_t)B_ * T_ * I_];
__device__ __nv_bfloat16 g_wih0hi[(size_t)G_ * I_];
__device__ __nv_bfloat16 g_wih0lo[(size_t)G_ * I_];
__device__ __nv_bfloat16 g_wih1hi[(size_t)G_ * H_];
__device__ __nv_bfloat16 g_wih1lo[(size_t)G_ * H_];
__device__ __nv_bfloat16 g_hs0hi[(size_t)T_ * B_ * H_];  // layer-0 outputs hi/lo (for proj)
__device__ __nv_bfloat16 g_hs0lo[(size_t)T_ * B_ * H_];
__device__ __half g_hf[2][B_ * H_];                // recurrent h, single fp16
__device__ float g_hlast[B_ * H_];                 // fp32 final h for FC
__device__ unsigned int g_cnt[8 * 32];             // 8 group counters, 128B padded
__device__ unsigned int g_super;                   // super counter (8 arrivals/step)

// ---------------- helpers ----------------
__device__ __forceinline__ void ldsm4(uint32_t* r, uint32_t addr) {
    asm volatile("ldmatrix.sync.aligned.m8n8.x4.shared.b16 {%0,%1,%2,%3}, [%4];"
        : "=r"(r[0]), "=r"(r[1]), "=r"(r[2]), "=r"(r[3]) : "r"(addr));
}
__device__ __forceinline__ void ldsm2(uint32_t* r, uint32_t addr) {
    asm volatile("ldmatrix.sync.aligned.m8n8.x2.shared.b16 {%0,%1}, [%2];"
        : "=r"(r[0]), "=r"(r[1]) : "r"(addr));
}
// bf16 mma (projections)
__device__ __forceinline__ void mma16816(float* c, const uint32_t* a, const uint32_t* b) {
    asm volatile("mma.sync.aligned.m16n8k16.row.col.f32.bf16.bf16.f32 "
        "{%0,%1,%2,%3}, {%4,%5,%6,%7}, {%8,%9}, {%0,%1,%2,%3};"
        : "+f"(c[0]), "+f"(c[1]), "+f"(c[2]), "+f"(c[3])
        : "r"(a[0]), "r"(a[1]), "r"(a[2]), "r"(a[3]), "r"(b[0]), "r"(b[1]));
}
// fp16 mma (recurrence)
__device__ __forceinline__ void mma16816h(float* c, const uint32_t* a, const uint32_t* b) {
    asm volatile("mma.sync.aligned.m16n8k16.row.col.f32.f16.f16.f32 "
        "{%0,%1,%2,%3}, {%4,%5,%6,%7}, {%8,%9}, {%0,%1,%2,%3};"
        : "+f"(c[0]), "+f"(c[1]), "+f"(c[2]), "+f"(c[3])
        : "r"(a[0]), "r"(a[1]), "r"(a[2]), "r"(a[3]), "r"(b[0]), "r"(b[1]));
}
__device__ __forceinline__ uint32_t cvta_s(const void* p) {
    return (uint32_t)__cvta_generic_to_shared(p);
}
__device__ __forceinline__ unsigned int ld_acq(const unsigned int* p) {
    unsigned int v;
    asm volatile("ld.acquire.gpu.u32 %0, [%1];" : "=r"(v) : "l"(p) : "memory");
    return v;
}
#define CP_ASYNC16(d, s) asm volatile("cp.async.cg.shared.global [%0], [%1], 16;" :: "r"(d), "l"(s))
#define CP_COMMIT()      asm volatile("cp.async.commit_group;" ::: "memory")
#define CP_WAIT2()       asm volatile("cp.async.wait_group 2;" ::: "memory")
#define CP_WAIT1()       asm volatile("cp.async.wait_group 1;" ::: "memory")
#define CP_WAIT0()       asm volatile("cp.async.wait_group 0;" ::: "memory")

// ---------------- init ----------------
__global__ void init_kernel() {
    int idx = blockIdx.x * blockDim.x + threadIdx.x;
    if (idx < 8 * 32) g_cnt[idx] = 0u;
    if (idx == 0) g_super = 0u;
    __half z = __float2half(0.f);
    int n = 2 * B_ * H_;
    __half* ph = (__half*)g_hf;
    for (int i = idx; i < n; i += gridDim.x * blockDim.x) ph[i] = z;
}

// ---------------- fp32 -> bf16 hi/lo split (projection operands) ------------
__global__ void split_kernel(const float* __restrict__ src,
                             __nv_bfloat16* __restrict__ hi,
                             __nv_bfloat16* __restrict__ lo, int n4) {
    int i = blockIdx.x * blockDim.x + threadIdx.x;
    if (i >= n4) return;
    float4 v = ((const float4*)src)[i];
    __nv_bfloat16 h0 = __float2bfloat16(v.x);
    __nv_bfloat16 h1 = __float2bfloat16(v.y);
    __nv_bfloat16 h2 = __float2bfloat16(v.z);
    __nv_bfloat16 h3 = __float2bfloat16(v.w);
    __nv_bfloat162 a, b;
    a.x = h0; a.y = h1; b.x = h2; b.y = h3;
    ((__nv_bfloat162*)hi)[2 * i] = a;
    ((__nv_bfloat162*)hi)[2 * i + 1] = b;
    a.x = __float2bfloat16(v.x - __bfloat162float(h0));
    a.y = __float2bfloat16(v.y - __bfloat162float(h1));
    b.x = __float2bfloat16(v.z - __bfloat162float(h2));
    b.y = __float2bfloat16(v.w - __bfloat162float(h3));
    ((__nv_bfloat162*)lo)[2 * i] = a;
    ((__nv_bfloat162*)lo)[2 * i + 1] = b;
}

// ---------------- hierarchical grid barrier (128 blocks, 8 groups of 16) ----
__device__ __forceinline__ void gridbar2(int t, int bid) {
    __threadfence();
    __syncthreads();
    if (threadIdx.x == 0) {
        unsigned int r = atomicAdd(&g_cnt[(bid >> 4) * 32], 1u);
        if ((r & 15u) == 15u) atomicAdd(&g_super, 1u);
        unsigned int tgt = 8u * (unsigned int)(t + 1);
        while (ld_acq(&g_super) < tgt) __nanosleep(32);
    }
    __syncthreads();
}

// ---------------- split-bf16 MMA projection GEMM (unchanged) ----------------
__global__ __launch_bounds__(256) void mma_xproj(
    const __nv_bfloat16* __restrict__ Ahi, const __nv_bfloat16* __restrict__ Alo,
    const __nv_bfloat16* __restrict__ Whi, const __nv_bfloat16* __restrict__ Wlo,
    const float* __restrict__ b1, const float* __restrict__ b2,
    float* __restrict__ Cout, int K, int mode)
{
    __shared__ __nv_bfloat16 sAhi[128 * 40], sAlo[128 * 40];
    __shared__ __nv_bfloat16 sBhi[64 * 40],  sBlo[64 * 40];
    __shared__ float sBias[64];

    int tid = threadIdx.x;
    int n0 = blockIdx.x * 64;
    int m0 = blockIdx.y * 128;
    int w = tid >> 5, lane = tid & 31;
    int r0 = w * 16;

    if (tid < 64) sBias[tid] = b1[n0 + tid] + b2[n0 + tid];

    float acc[8][4];
#pragma unroll
    for (int i = 0; i < 8; i++)
#pragma unroll
        for (int j = 0; j < 4; j++) acc[i][j] = 0.f;

    size_t arow[2]; int aoff[2];
#pragma unroll
    for (int it = 0; it < 2; it++) {
        int idx = tid + it * 256;
        int r = idx >> 2, seg = idx & 3;
        int m = m0 + r;
        arow[it] = (mode == 0) ? ((size_t)(m & 63) * T_ + (size_t)(m >> 6)) * (size_t)K + (size_t)(seg * 8)
                               : (size_t)m * (size_t)K + (size_t)(seg * 8);
        aoff[it] = r * 40 + seg * 8;
    }
    int br = tid >> 2, bseg = tid & 3;
    size_t brow = (size_t)(n0 + br) * (size_t)K + (size_t)(bseg * 8);
    int boff = br * 40 + bseg * 8;

    int lrA = (lane & 7) + (lane & 8);
    int lcA = (lane & 16) ? 8 : 0;
    uint32_t aHiB = cvta_s(&sAhi[(r0 + lrA) * 40 + lcA]);
    uint32_t aLoB = cvta_s(&sAlo[(r0 + lrA) * 40 + lcA]);
    int lrB = lane & 7;
    int lcB = (lane & 8) ? 8 : 0;
    uint32_t bHiB = cvta_s(&sBhi[lrB * 40 + lcB]);
    uint32_t bLoB = cvta_s(&sBlo[lrB * 40 + lcB]);

    for (int kc = 0; kc < K; kc += 32) {
        __syncthreads();
#pragma unroll
        for (int it = 0; it < 2; it++) {
            *(uint4*)&sAhi[aoff[it]] = *(const uint4*)(Ahi + arow[it] + kc);
            *(uint4*)&sAlo[aoff[it]] = *(const uint4*)(Alo + arow[it] + kc);
        }
        *(uint4*)&sBhi[boff] = *(const uint4*)(Whi + brow + kc);
        *(uint4*)&sBlo[boff] = *(const uint4*)(Wlo + brow + kc);
        __syncthreads();
#pragma unroll
        for (int ks = 0; ks < 2; ks++) {
            int k0 = ks * 16;
            uint32_t ah[4], al[4];
            ldsm4(ah, aHiB + (uint32_t)(k0 * 2));
            ldsm4(al, aLoB + (uint32_t)(k0 * 2));
#pragma unroll
            for (int nt = 0; nt < 8; nt++) {
                uint32_t bh[2], bl[2];
                uint32_t off = (uint32_t)(nt * 8 * 40 + k0) * 2u;
                ldsm2(bh, bHiB + off);
                ldsm2(bl, bLoB + off);
                mma16816(acc[nt], ah, bh);
                mma16816(acc[nt], ah, bl);
                mma16816(acc[nt], al, bh);
            }
        }
    }

    int g = lane >> 2, tq = lane & 3;
#pragma unroll
    for (int nt = 0; nt < 8; nt++) {
        int col = nt * 8 + tq * 2;
        float bb0 = sBias[col], bb1 = sBias[col + 1];
        size_t mA = (size_t)(m0 + r0 + g) * G_ + n0 + col;
        size_t mB = (size_t)(m0 + r0 + g + 8) * G_ + n0 + col;
        float2 v0 = make_float2(acc[nt][0] + bb0, acc[nt][1] + bb1);
        float2 v1 = make_float2(acc[nt][2] + bb0, acc[nt][3] + bb1);
        *(float2*)&Cout[mA] = v0;
        *(float2*)&Cout[mB] = v1;
    }
}

// ---------------- persistent LSTM recurrence: single-term fp16, k-split -----
// 128 blocks x 512 threads. Warp w: rowg=w&3 (16 rows), colg=(w>>2)&1 (16 cols),
// ks=w>>3 (k-half of each 128-col chunk). Block owns 8 h-cols (32 gate-cols).
// W_hh single fp16 resident in SMEM; h (fp16) 4-buffer cp.async pipeline.
extern __shared__ char smem_dyn[];
__global__ __launch_bounds__(512) void lstm_recur_mma(
    const float* __restrict__ xproj,   // [T][B][4H] fp32
    const float* __restrict__ Whh,     // [4H][H] fp32
    __nv_bfloat16* __restrict__ hshi, __nv_bfloat16* __restrict__ hslo,
    int writeSeq, int writeLast)
{
    __half* sW = (__half*)smem_dyn;                        // 32 x 1032
    __half* sH = sW + 32 * 1032;                           // 4 bufs x 64x136
    float* sG  = (float*)(sH + 4 * 64 * 136);              // ks=0 partials, 64x32
    float* sG2 = sG + 64 * 32;                             // ks=1 partials
    float* sC  = sG2 + 64 * 32;                            // 64 x 8 cell state

    int tid = threadIdx.x, w = tid >> 5, lane = tid & 31;
    int bid = blockIdx.x;
    int jbase = bid * 8;

    // load W_hh into SMEM fp16 (once)
    for (int i = tid; i < 32 * 1024; i += 512) {
        int n = i >> 10, k = i & 1023;
        float v = Whh[(size_t)((n >> 3) * H_ + jbase + (n & 7)) * H_ + k];
        sW[n * 1032 + k] = __float2half(v);
    }
    if (tid < 512) sC[tid] = 0.f;

    int rowg = w & 3, colg = (w >> 2) & 1, ks = w >> 3;
    int r0 = rowg * 16;
    int lrA = (lane & 7) + (lane & 8);
    int lcA = (lane & 16) ? 8 : 0;
    uint32_t aB[4], dstB[4];
#pragma unroll
    for (int bf = 0; bf < 4; bf++) {
        aB[bf]  = cvta_s(&sH[bf * 8704 + (r0 + lrA) * 136 + ks * 64 + lcA]);
        dstB[bf] = cvta_s(&sH[bf * 8704]);
    }
    // B bases: two col-tiles (8 gate-cols each) at colg*16 and colg*16+8
    int bRow = (lane & 7);
    int bK   = ((lane >> 3) & 3) * 8;
    uint32_t bW0 = cvta_s(&sW[(colg * 16 + bRow) * 1032 + ks * 64 + bK]);
    uint32_t bW1 = bW0 + (uint32_t)(8 * 1032 * 2);

    // cp.async mapping: 16KB/chunk = 1024 x 16B; 2 per thread
    int pr[2], ps[2];
#pragma unroll
    for (int it = 0; it < 2; it++) {
        int idx = tid + it * 512;
        pr[it] = idx >> 4;            // row 0..63
        ps[it] = (idx & 15) * 8;      // col segment (8 fp16 = 16B)
    }

    int g = lane >> 2, tq = lane & 3;
    int colA = colg * 16 + tq * 2;    // col-tile 0 cols
    int colB = colA + 8;              // col-tile 1 cols
    int bA = r0 + g, bB = bA + 8;
    float* sGx = ks ? sG2 : sG;

    // cell-update thread mapping + xproj addresses
    int cb = tid >> 3, cj = tid & 7;
    const float* xpb = xproj + (size_t)cb * G_ + jbase + cj;

    __syncthreads();

#define PREF(ch, bf) do {                                                     \
    int kc_ = (ch) * 128;                                                     \
    _Pragma("unroll")                                                         \
    for (int it = 0; it < 2; it++) {                                          \
        uint32_t so = (uint32_t)(pr[it] * 136 + ps[it]) * 2u;                 \
        CP_ASYNC16(dstB[(bf)] + so, hr + pr[it] * H_ + kc_ + ps[it]);         \
    }                                                                         \
    CP_COMMIT();                                                              \
} while (0)

    for (int t = 0; t < T_; t++) {
        const __half* hr = g_hf[t & 1];

        PREF(0, 0);
        PREF(1, 1);

        // prefetch this step's xproj gate values (cell-update layout)
        size_t xt = (size_t)t * B_ * G_;
        float xg0 = xpb[xt];
        float xg1 = xpb[xt + 1 * H_];
        float xg2 = xpb[xt + 2 * H_];
        float xg3 = xpb[xt + 3 * H_];

        float acc[2][4];
#pragma unroll
        for (int ct = 0; ct < 2; ct++)
#pragma unroll
            for (int j = 0; j < 4; j++) acc[ct][j] = 0.f;

        for (int ch = 0; ch < 8; ch++) {
            int cur = ch & 3;
            if (ch < 6) { PREF(ch + 2, (ch + 2) & 3); CP_WAIT2(); }
            else if (ch == 6) { CP_WAIT1(); }
            else { CP_WAIT0(); }
            __syncthreads();

            int kc = ch * 128;
#pragma unroll
            for (int kg = 0; kg < 2; kg++) {
                uint32_t koff = (uint32_t)(kg * 32) * 2u;
                uint32_t a0[4], a1[4];
                ldsm4(a0, aB[cur] + koff);
                ldsm4(a1, aB[cur] + koff + 32);
                uint32_t bo = (uint32_t)(kc + kg * 32) * 2u;
                uint32_t bh[4], bh1[4];
                ldsm4(bh, bW0 + bo);
                ldsm4(bh1, bW1 + bo);
                mma16816h(acc[0], a0, bh);
                mma16816h(acc[0], a1, bh + 2);
                mma16816h(acc[1], a0, bh1);
                mma16816h(acc[1], a1, bh1 + 2);
            }
        }

        // partial gate sums -> sG (ks=0) / sG2 (ks=1)
        {
            *(float2*)&sGx[bA * 32 + colA] = make_float2(acc[0][0], acc[0][1]);
            *(float2*)&sGx[bB * 32 + colA] = make_float2(acc[0][2], acc[0][3]);
            *(float2*)&sGx[bA * 32 + colB] = make_float2(acc[1][0], acc[1][1]);
            *(float2*)&sGx[bB * 32 + colB] = make_float2(acc[1][2], acc[1][3]);
        }
        __syncthreads();

        // cell update: 512 cells/block, 1 per thread
        __half* hw = g_hf[(t + 1) & 1];
        {
            float iv = sG[cb * 32 + cj]      + sG2[cb * 32 + cj]      + xg0;
            float fv = sG[cb * 32 + 8 + cj]  + sG2[cb * 32 + 8 + cj]  + xg1;
            float gv = sG[cb * 32 + 16 + cj] + sG2[cb * 32 + 16 + cj] + xg2;
            float ov = sG[cb * 32 + 24 + cj] + sG2[cb * 32 + 24 + cj] + xg3;
            float ig = 1.f / (1.f + expf(-iv));
            float fg = 1.f / (1.f + expf(-fv));
            float gg = tanhf(gv);
            float og = 1.f / (1.f + expf(-ov));
            float cc = fg * sC[cb * 8 + cj] + ig * gg;
            sC[cb * 8 + cj] = cc;
            float hh = og * tanhf(cc);
            int hidx = cb * H_ + jbase + cj;
            hw[hidx] = __float2half(hh);
            if (writeSeq) {
                __nv_bfloat16 hb = __float2bfloat16(hh);
                size_t sidx = ((size_t)t * B_ + cb) * H_ + jbase + cj;
                hshi[sidx] = hb;
                hslo[sidx] = __float2bfloat16(hh - __bfloat162float(hb));
            }
            if (writeLast && t == T_ - 1) g_hlast[hidx] = hh;
        }
        if (t < T_ - 1) gridbar2(t, bid);   // last step: kernel boundary syncs
    }
#undef PREF
}

// ---------------- FC head ----------------
__global__ __launch_bounds__(256) void fc_kernel(
    const float* __restrict__ fc_w, const float* __restrict__ fc_b,
    float* __restrict__ out)
{
    __shared__ float sh[H_];
    int b = blockIdx.x, tid = threadIdx.x;
    const float* hlast = g_hlast + (size_t)b * H_;
    for (int i = tid; i < H_; i += 256) sh[i] = hlast[i];
    __syncthreads();
    int o = tid;
    const float* wrow = fc_w + (size_t)o * H_;
    float acc = fc_b[o];
#pragma unroll 8
    for (int k = 0; k < H_; k++) acc += sh[k] * wrow[k];
    out[b * O_ + o] = acc;
}

// ---------------- launch ----------------
// W: 32*1032 fp16 + h: 4*64*136 fp16 + sG/sG2: 2*2048 f32 + sC: 512 f32
#define SMEM_REC ((32*1032 + 4*64*136) * 2 + (2*64*32 + 64*8) * 4)

extern "C" void kernel_launch(void* const* d_in, const int* in_sizes, int n_in,
                              void* d_out, int out_size) {
    (void)in_sizes; (void)n_in; (void)out_size;
    const float* x     = (const float*)d_in[0];
    const float* W_ih0 = (const float*)d_in[1];
    const float* W_hh0 = (const float*)d_in[2];
    const float* b_ih0 = (const float*)d_in[3];
    const float* b_hh0 = (const float*)d_in[4];
    const float* W_ih1 = (const float*)d_in[5];
    const float* W_hh1 = (const float*)d_in[6];
    const float* b_ih1 = (const float*)d_in[7];
    const float* b_hh1 = (const float*)d_in[8];
    const float* fc_w  = (const float*)d_in[9];
    const float* fc_b  = (const float*)d_in[10];
    float* out = (float*)d_out;

    float *xp0, *xp1;
    __nv_bfloat16 *xhi, *xlo, *w0hi, *w0lo, *w1hi, *w1lo, *hs0hi, *hs0lo;
    cudaGetSymbolAddress((void**)&xp0, g_xproj0);
    cudaGetSymbolAddress((void**)&xp1, g_xproj1);
    cudaGetSymbolAddress((void**)&xhi, g_xhi);
    cudaGetSymbolAddress((void**)&xlo, g_xlo);
    cudaGetSymbolAddress((void**)&w0hi, g_wih0hi);
    cudaGetSymbolAddress((void**)&w0lo, g_wih0lo);
    cudaGetSymbolAddress((void**)&w1hi, g_wih1hi);
    cudaGetSymbolAddress((void**)&w1lo, g_wih1lo);
    cudaGetSymbolAddress((void**)&hs0hi, g_hs0hi);
    cudaGetSymbolAddress((void**)&hs0lo, g_hs0lo);

    cudaFuncSetAttribute(lstm_recur_mma,
        cudaFuncAttributeMaxDynamicSharedMemorySize, SMEM_REC);

    // splits (projection operands, bf16 3-term)
    int nx4 = B_ * T_ * I_ / 4;
    split_kernel<<<(nx4 + 255) / 256, 256>>>(x, xhi, xlo, nx4);
    int nw04 = G_ * I_ / 4;
    split_kernel<<<(nw04 + 255) / 256, 256>>>(W_ih0, w0hi, w0lo, nw04);
    int nw14 = G_ * H_ / 4;
    split_kernel<<<(nw14 + 255) / 256, 256>>>(W_ih1, w1hi, w1lo, nw14);

    dim3 pgrid(G_ / 64, (B_ * T_) / 128);

    // layer 0
    mma_xproj<<<pgrid, 256>>>(xhi, xlo, w0hi, w0lo, b_ih0, b_hh0, xp0, I_, 0);
    init_kernel<<<64, 256>>>();
    lstm_recur_mma<<<128, 512, SMEM_REC>>>(xp0, W_hh0, hs0hi, hs0lo, 1, 0);

    // layer 1
    mma_xproj<<<pgrid, 256>>>(hs0hi, hs0lo, w1hi, w1lo, b_ih1, b_hh1, xp1, H_, 1);
    init_kernel<<<64, 256>>>();
    lstm_recur_mma<<<128, 512, SMEM_REC>>>(xp1, W_hh1, hs0hi, hs0lo, 0, 1);

    // head
    fc_kernel<<<64, 256>>>(fc_w, fc_b, out);
}